// round 3
// baseline (speedup 1.0000x reference)
#include <cuda_runtime.h>
#include <cstdint>

#define H        768
#define CK       16                 // K-chunk size (floats)
#define NCH      (H / CK)           // 48 chunks
#define RPW      32                 // rows per warp tile (1 row per lane)
#define PADW     20                 // floats per row slot in smem (16 + 4 pad -> 80B, conflict-free)
#define WBUF     (RPW * PADW)       // 640 floats per buffer per warp
#define WARPS    8                  // warps per CTA (256 threads)

// Packed weights: c_W4[k][q] is a float4 covering channels 4q..4q+3 of the
// 18-channel (padded) fused output. 9 channel-pairs -> 4 full float4 + pair 8.
__constant__ float4 c_W4[H][5];
__constant__ float  c_bias[20];

__device__ float2 g_pack[H * 10];
__device__ float  g_biasStage[20];

// Warp-private staging: [warp][2 buffers][640 floats] = 40960 B static smem.
__shared__ float xs[WARPS][2][WBUF];

// ---------------------------------------------------------------------------
// Prep: transpose/pack weights into [k][pair] layout + biases.
// Channel order: a0,a1 | b0..b3 | c1_0,c1_1 | c2_0..2 | c3_0..3 | c4_0,c4_1 | pad
// ---------------------------------------------------------------------------
__global__ void prep_kernel(
    const float* __restrict__ Wa,  const float* __restrict__ ba,
    const float* __restrict__ Wb,  const float* __restrict__ bb,
    const float* __restrict__ Wc1, const float* __restrict__ bc1,
    const float* __restrict__ Wc2, const float* __restrict__ bc2,
    const float* __restrict__ Wc3, const float* __restrict__ bc3,
    const float* __restrict__ Wc4, const float* __restrict__ bc4)
{
    int id = blockIdx.x * blockDim.x + threadIdx.x;

    auto getw = [&](int ch, int k) -> float {
        if (ch < 2)  return Wa [ ch        * H + k];
        if (ch < 6)  return Wb [(ch - 2)  * H + k];
        if (ch < 8)  return Wc1[(ch - 6)  * H + k];
        if (ch < 11) return Wc2[(ch - 8)  * H + k];
        if (ch < 15) return Wc3[(ch - 11) * H + k];
        if (ch < 17) return Wc4[(ch - 15) * H + k];
        return 0.0f;
    };

    if (id < H * 10) {
        int k = id / 10, p = id % 10;
        g_pack[k * 10 + p] = make_float2(getw(2 * p, k), getw(2 * p + 1, k));
    }
    if (id < 20) {
        int ch = id; float b;
        if      (ch < 2)  b = ba [ch];
        else if (ch < 6)  b = bb [ch - 2];
        else if (ch < 8)  b = bc1[ch - 6];
        else if (ch < 11) b = bc2[ch - 8];
        else if (ch < 15) b = bc3[ch - 11];
        else if (ch < 17) b = bc4[ch - 15];
        else              b = 0.0f;
        g_biasStage[ch] = b;
    }
}

// ---------------------------------------------------------------------------
// Packed fp32x2 FMA (SASS FFMA2) — 2 fp32 FMAs per instruction.
// ---------------------------------------------------------------------------
__device__ __forceinline__ void ffma2(float2& d, const float2 a, const float2 b)
{
    asm("fma.rn.f32x2 %0, %1, %2, %0;"
        : "+l"(reinterpret_cast<unsigned long long&>(d))
        : "l"(reinterpret_cast<const unsigned long long&>(a)),
          "l"(reinterpret_cast<const unsigned long long&>(b)));
}

__device__ __forceinline__ void cp16(uint32_t saddr, const void* gptr)
{
    asm volatile("cp.async.cg.shared.global [%0], [%1], 16;" :: "r"(saddr), "l"(gptr));
}
__device__ __forceinline__ void cp_commit() { asm volatile("cp.async.commit_group;"); }
template <int N>
__device__ __forceinline__ void cp_wait()   { asm volatile("cp.async.wait_group %0;" :: "n"(N)); }

// ---------------------------------------------------------------------------
// Main kernel: one 32-row tile per warp, warp-private double-buffered staging,
// no CTA barriers. 4 CTAs/SM (static 40KB smem, <=64 regs) -> 32 warps/SM.
// ---------------------------------------------------------------------------
__global__ void __launch_bounds__(256, 4)
main_kernel(const float* __restrict__ x, float* __restrict__ out, int B, int ntiles)
{
    const int wid  = threadIdx.x >> 5;
    const int lane = threadIdx.x & 31;
    const int tile = blockIdx.x * WARPS + wid;
    if (tile >= ntiles) return;

    const int    row0 = tile * RPW;
    const float* gx   = x + (size_t)row0 * H;
    const uint32_t sb = (uint32_t)__cvta_generic_to_shared(&xs[wid][0][0]);

    // cp.async mapping: 4 lanes per row -> each warp-inst hits 8 rows x 64B
    const int crow  = lane >> 2;    // 0..7
    const int cpart = lane & 3;     // 0..3  (16B each)

    float2 acc[9];
    #pragma unroll
    for (int p = 0; p < 9; ++p) acc[p] = make_float2(0.f, 0.f);

    // --- stage chunk 0 ---
    #pragma unroll
    for (int i = 0; i < 4; ++i) {
        const int row = i * 8 + crow;
        if (row0 + row < B)
            cp16(sb + row * (PADW * 4) + cpart * 16,
                 gx + (size_t)row * H + cpart * 4);
    }
    cp_commit();

    for (int c = 0; c < NCH; ++c) {
        // prefetch chunk c+1 into the other buffer
        if (c + 1 < NCH) {
            const int nb = (c + 1) & 1;
            const float* gsrc = gx + (c + 1) * CK;
            #pragma unroll
            for (int i = 0; i < 4; ++i) {
                const int row = i * 8 + crow;
                if (row0 + row < B)
                    cp16(sb + nb * (WBUF * 4) + row * (PADW * 4) + cpart * 16,
                         gsrc + (size_t)row * H + cpart * 4);
            }
            cp_commit();
            cp_wait<1>();
        } else {
            cp_wait<0>();
        }
        __syncwarp();   // all lanes' cp for chunk c complete before any lane reads

        // compute chunk c: lane = row, 16 k-values via 4x float4 from smem
        const float4* xr =
            reinterpret_cast<const float4*>(&xs[wid][c & 1][lane * PADW]);
        const int kchunk = c * CK;
        #pragma unroll
        for (int rg = 0; rg < 4; ++rg) {
            const float4 xv = xr[rg];
            const int kb = kchunk + rg * 4;
            #pragma unroll
            for (int j = 0; j < 4; ++j) {
                const float xk = (j == 0) ? xv.x : (j == 1) ? xv.y
                               : (j == 2) ? xv.z : xv.w;
                const float2 xd = make_float2(xk, xk);
                const float4* wk = c_W4[kb + j];         // warp-uniform -> LDCU.128
                #pragma unroll
                for (int p = 0; p < 4; ++p) {
                    const float4 w = wk[p];
                    ffma2(acc[2 * p],     xd, make_float2(w.x, w.y));
                    ffma2(acc[2 * p + 1], xd, make_float2(w.z, w.w));
                }
                const float4 w4 = wk[4];
                ffma2(acc[8], xd, make_float2(w4.x, w4.y));
            }
        }
        __syncwarp();   // no lane overwrites this buffer (iter c+2) until all read it
    }

    // --- epilogue: bias, routing, masked stores ---
    const int r = row0 + lane;
    if (r < B) {
        float v[18];
        #pragma unroll
        for (int p = 0; p < 9; ++p) {
            v[2 * p]     = acc[p].x + c_bias[2 * p];
            v[2 * p + 1] = acc[p].y + c_bias[2 * p + 1];
        }
        const bool active = v[1] > v[0];            // argmax(out_a) != 0 (tie -> 0)

        ((float2*)out)[r] = make_float2(v[0], v[1]);     // out_a

        int pb = 0; float best = v[2];
        if (v[3] > best) { pb = 1; best = v[3]; }
        if (v[4] > best) { pb = 2; best = v[4]; }
        if (v[5] > best) { pb = 3; best = v[5]; }

        float* ob = out + 2 * (size_t)B + 5 * (size_t)r;  // out_b
        ob[0] = 0.0f;
        #pragma unroll
        for (int j = 0; j < 4; ++j) ob[j + 1] = active ? v[2 + j] : 0.0f;

        float* oc = out + 7 * (size_t)B + 11 * (size_t)r; // out_c
        #pragma unroll
        for (int j = 0; j < 11; ++j) {
            const int hd = (j < 2) ? 0 : (j < 5) ? 1 : (j < 9) ? 2 : 3;
            oc[j] = (active && hd == pb) ? v[6 + j] : 0.0f;
        }
    }
}

// ---------------------------------------------------------------------------
extern "C" void kernel_launch(void* const* d_in, const int* in_sizes, int n_in,
                              void* d_out, int out_size)
{
    const float* x = (const float*)d_in[0];
    const int B = in_sizes[0] / H;

    prep_kernel<<<30, 256>>>(
        (const float*)d_in[1],  (const float*)d_in[2],
        (const float*)d_in[3],  (const float*)d_in[4],
        (const float*)d_in[5],  (const float*)d_in[6],
        (const float*)d_in[7],  (const float*)d_in[8],
        (const float*)d_in[9],  (const float*)d_in[10],
        (const float*)d_in[11], (const float*)d_in[12]);

    void* packAddr = nullptr;  cudaGetSymbolAddress(&packAddr, g_pack);
    void* biasAddr = nullptr;  cudaGetSymbolAddress(&biasAddr, g_biasStage);
    cudaMemcpyToSymbolAsync(c_W4,  packAddr, sizeof(float2) * H * 10, 0,
                            cudaMemcpyDeviceToDevice, 0);
    cudaMemcpyToSymbolAsync(c_bias, biasAddr, sizeof(float) * 20, 0,
                            cudaMemcpyDeviceToDevice, 0);

    const int ntiles = (B + RPW - 1) / RPW;             // 4096 for B=131072
    const int grid   = (ntiles + WARPS - 1) / WARPS;    // 512 -> single wave @4 CTA/SM

    main_kernel<<<grid, WARPS * 32>>>(x, (float*)d_out, B, ntiles);
}

// round 4
// speedup vs baseline: 1.9518x; 1.9518x over previous
#include <cuda_runtime.h>
#include <cstdint>

#define H        768
#define CK       32                  // K-chunk floats per stage (128 B/row)
#define NCH      (H / CK)            // 24 chunks
#define DEPTH    3                   // cp.async pipeline stages
#define RPW      32                  // rows per warp tile (1 row per lane)
#define RSTRIDE  36                  // floats per row slot (32 + 4 pad, conflict-free LDS.128)
#define CHUNK_FLOATS (RPW * RSTRIDE) // 1152
#define CHUNK_BYTES  (CHUNK_FLOATS * 4)
#define WARPS    4                   // warps per CTA (128 threads)
#define SMEM_BYTES (WARPS * DEPTH * CHUNK_BYTES)   // 55296 B/CTA -> 4 CTAs/SM

// 17 fused channels: a0,a1 | b0..b3 | c1_0,c1_1 | c2_0..2 | c3_0..3 | c4_0,c4_1
// c_W4[k][p] = channels 4p..4p+3 (pairs 2p,2p+1); c_W1[k] = channel 16.
__constant__ float4 c_W4[H][4];
__constant__ float  c_W1[H];
__constant__ float  c_bias[17];

__device__ float4 g_pack4[H * 4];
__device__ float  g_pack1[H];
__device__ float  g_biasStage[17];

// ---------------------------------------------------------------------------
__global__ void prep_kernel(
    const float* __restrict__ Wa,  const float* __restrict__ ba,
    const float* __restrict__ Wb,  const float* __restrict__ bb,
    const float* __restrict__ Wc1, const float* __restrict__ bc1,
    const float* __restrict__ Wc2, const float* __restrict__ bc2,
    const float* __restrict__ Wc3, const float* __restrict__ bc3,
    const float* __restrict__ Wc4, const float* __restrict__ bc4)
{
    int id = blockIdx.x * blockDim.x + threadIdx.x;

    auto getw = [&](int ch, int k) -> float {
        if (ch < 2)  return Wa [ ch        * H + k];
        if (ch < 6)  return Wb [(ch - 2)  * H + k];
        if (ch < 8)  return Wc1[(ch - 6)  * H + k];
        if (ch < 11) return Wc2[(ch - 8)  * H + k];
        if (ch < 15) return Wc3[(ch - 11) * H + k];
        return Wc4[(ch - 15) * H + k];              // ch 15,16
    };

    if (id < H * 4) {
        int k = id >> 2, p = id & 3;
        g_pack4[id] = make_float4(getw(4 * p, k),     getw(4 * p + 1, k),
                                  getw(4 * p + 2, k), getw(4 * p + 3, k));
    }
    if (id < H) g_pack1[id] = getw(16, id);
    if (id < 17) {
        int ch = id; float b;
        if      (ch < 2)  b = ba [ch];
        else if (ch < 6)  b = bb [ch - 2];
        else if (ch < 8)  b = bc1[ch - 6];
        else if (ch < 11) b = bc2[ch - 8];
        else if (ch < 15) b = bc3[ch - 11];
        else              b = bc4[ch - 15];
        g_biasStage[ch] = b;
    }
}

// ---------------------------------------------------------------------------
__device__ __forceinline__ void ffma2(float2& d, const float2 a, const float2 b)
{
    asm("fma.rn.f32x2 %0, %1, %2, %0;"
        : "+l"(reinterpret_cast<unsigned long long&>(d))
        : "l"(reinterpret_cast<const unsigned long long&>(a)),
          "l"(reinterpret_cast<const unsigned long long&>(b)));
}

__device__ __forceinline__ void cp16(uint32_t saddr, const void* gptr)
{
    asm volatile("cp.async.cg.shared.global [%0], [%1], 16;"
                 :: "r"(saddr), "l"(gptr) : "memory");
}
__device__ __forceinline__ void cp_commit()
{
    asm volatile("cp.async.commit_group;" ::: "memory");
}
template <int N>
__device__ __forceinline__ void cp_wait()
{
    asm volatile("cp.async.wait_group %0;" :: "n"(N) : "memory");
}

// ---------------------------------------------------------------------------
// One 32-row tile per warp; warp-private 3-deep cp.async ring; no CTA barriers.
// ---------------------------------------------------------------------------
extern __shared__ float xs[];

__global__ void __launch_bounds__(WARPS * 32, 4)
main_kernel(const float* __restrict__ x, float* __restrict__ out, int B, int ntiles)
{
    const int wid  = threadIdx.x >> 5;
    const int lane = threadIdx.x & 31;
    const int tile = blockIdx.x * WARPS + wid;
    if (tile >= ntiles) return;

    const int    row0 = tile * RPW;
    const float* gx   = x + (size_t)row0 * H;

    const uint32_t sb =
        (uint32_t)__cvta_generic_to_shared(xs) + wid * (DEPTH * CHUNK_BYTES);
    float* xw = xs + wid * (DEPTH * CHUNK_FLOATS);

    // cp.async mapping: 8 lanes cover one 128 B row-segment (1 full line/wf).
    const int crow  = lane >> 3;   // 0..3
    const int cpart = lane & 7;    // 0..7  (16 B each)

    // each cp16 loop iteration i loads rows {i*4+crow} for i=0..7 -> 32 rows
    auto load_chunk = [&](int c, int d) {
        const float* gsrc = gx + c * CK + (size_t)crow * H + cpart * 4;
        const uint32_t dst0 = sb + d * CHUNK_BYTES + crow * (RSTRIDE * 4) + cpart * 16;
        #pragma unroll
        for (int i = 0; i < 8; ++i) {
            if (row0 + i * 4 + crow < B)
                cp16(dst0 + i * 4 * (RSTRIDE * 4), gsrc + (size_t)(i * 4) * H);
        }
    };

    float2 acc[8];
    #pragma unroll
    for (int p = 0; p < 8; ++p) acc[p] = make_float2(0.f, 0.f);
    float acc16 = 0.f;

    // prime the pipeline: stages 0..2
    #pragma unroll
    for (int d = 0; d < DEPTH; ++d) { load_chunk(d, d); cp_commit(); }

    #pragma unroll 3
    for (int c = 0; c < NCH; ++c) {
        cp_wait<DEPTH - 1>();   // chunk c resident (oldest group retired)
        __syncwarp();

        const float4* xr =
            reinterpret_cast<const float4*>(xw + (c % DEPTH) * CHUNK_FLOATS
                                               + lane * RSTRIDE);
        const int kc = c * CK;
        #pragma unroll
        for (int rg = 0; rg < 8; ++rg) {
            const float4 xv = xr[rg];
            const int kb = kc + rg * 4;
            #pragma unroll
            for (int j = 0; j < 4; ++j) {
                const float  xk = (j == 0) ? xv.x : (j == 1) ? xv.y
                               : (j == 2) ? xv.z : xv.w;
                const float2 xd = make_float2(xk, xk);
                const int    k  = kb + j;
                #pragma unroll
                for (int p = 0; p < 4; ++p) {
                    const float4 w = c_W4[k][p];        // warp-uniform -> LDCU.128
                    ffma2(acc[2 * p],     xd, make_float2(w.x, w.y));
                    ffma2(acc[2 * p + 1], xd, make_float2(w.z, w.w));
                }
                acc16 = fmaf(xk, c_W1[k], acc16);
            }
        }
        __syncwarp();           // all lanes done reading before stage reuse

        if (c + DEPTH < NCH) load_chunk(c + DEPTH, c % DEPTH);
        cp_commit();            // empty groups keep wait_group counting exact
    }

    // --- epilogue: bias, routing, masked scattered stores ---
    const int r = row0 + lane;
    if (r < B) {
        float v[17];
        #pragma unroll
        for (int p = 0; p < 8; ++p) {
            v[2 * p]     = acc[p].x + c_bias[2 * p];
            v[2 * p + 1] = acc[p].y + c_bias[2 * p + 1];
        }
        v[16] = acc16 + c_bias[16];

        const bool active = v[1] > v[0];              // argmax(out_a) != 0

        ((float2*)out)[r] = make_float2(v[0], v[1]);  // out_a

        int pb = 0; float best = v[2];
        if (v[3] > best) { pb = 1; best = v[3]; }
        if (v[4] > best) { pb = 2; best = v[4]; }
        if (v[5] > best) { pb = 3; best = v[5]; }

        float* ob = out + 2 * (size_t)B + 5 * (size_t)r;   // out_b
        ob[0] = 0.0f;
        #pragma unroll
        for (int j = 0; j < 4; ++j) ob[j + 1] = active ? v[2 + j] : 0.0f;

        float* oc = out + 7 * (size_t)B + 11 * (size_t)r;  // out_c
        #pragma unroll
        for (int j = 0; j < 11; ++j) {
            const int hd = (j < 2) ? 0 : (j < 5) ? 1 : (j < 9) ? 2 : 3;
            oc[j] = (active && hd == pb) ? v[6 + j] : 0.0f;
        }
    }
}

// ---------------------------------------------------------------------------
extern "C" void kernel_launch(void* const* d_in, const int* in_sizes, int n_in,
                              void* d_out, int out_size)
{
    const float* x = (const float*)d_in[0];
    const int B = in_sizes[0] / H;

    prep_kernel<<<12, 256>>>(
        (const float*)d_in[1],  (const float*)d_in[2],
        (const float*)d_in[3],  (const float*)d_in[4],
        (const float*)d_in[5],  (const float*)d_in[6],
        (const float*)d_in[7],  (const float*)d_in[8],
        (const float*)d_in[9],  (const float*)d_in[10],
        (const float*)d_in[11], (const float*)d_in[12]);

    void* p4 = nullptr; cudaGetSymbolAddress(&p4, g_pack4);
    void* p1 = nullptr; cudaGetSymbolAddress(&p1, g_pack1);
    void* pb = nullptr; cudaGetSymbolAddress(&pb, g_biasStage);
    cudaMemcpyToSymbolAsync(c_W4,   p4, sizeof(float4) * H * 4, 0,
                            cudaMemcpyDeviceToDevice, 0);
    cudaMemcpyToSymbolAsync(c_W1,   p1, sizeof(float) * H, 0,
                            cudaMemcpyDeviceToDevice, 0);
    cudaMemcpyToSymbolAsync(c_bias, pb, sizeof(float) * 17, 0,
                            cudaMemcpyDeviceToDevice, 0);

    const int ntiles = (B + RPW - 1) / RPW;            // 4096 for B=131072
    const int grid   = (ntiles + WARPS - 1) / WARPS;   // 1024 CTAs

    cudaFuncSetAttribute(main_kernel,
                         cudaFuncAttributeMaxDynamicSharedMemorySize, SMEM_BYTES);
    main_kernel<<<grid, WARPS * 32, SMEM_BYTES>>>(x, (float*)d_out, B, ntiles);
}

// round 5
// speedup vs baseline: 2.1347x; 1.0937x over previous
#include <cuda_runtime.h>
#include <cstdint>

#define H        768
#define CK       16                    // K floats per pipeline stage (64 B/row)
#define NCH      (H / CK)              // 48 chunks
#define DEPTH    2                     // cp.async ring stages
#define WROWS    128                   // rows per warp pass (4 per lane)
#define RSTRIDE  20                    // floats per row slot (16 + 4 pad; conflict-free)
#define ROWB     (RSTRIDE * 4)         // 80 B
#define CHUNK_FLOATS (WROWS * RSTRIDE) // 2560
#define CHUNK_BYTES  (CHUNK_FLOATS * 4)
#define WARPS    4                     // warps per CTA
#define SMEM_BYTES (WARPS * DEPTH * CHUNK_BYTES)   // 81920 B -> 2 CTAs/SM

// 17 fused channels: a0,a1 | b0..b3 | c1_0,c1_1 | c2_0..2 | c3_0..3 | c4_0,c4_1
__constant__ float4 c_W4[H][4];   // channels 0..15
__constant__ float  c_W1[H];      // channel 16
__constant__ float  c_bias[17];

__device__ float4 g_pack4[H * 4];
__device__ float  g_pack1[H];
__device__ float  g_biasStage[17];
__device__ unsigned int g_ticket;

// ---------------------------------------------------------------------------
__global__ void prep_kernel(
    const float* __restrict__ Wa,  const float* __restrict__ ba,
    const float* __restrict__ Wb,  const float* __restrict__ bb,
    const float* __restrict__ Wc1, const float* __restrict__ bc1,
    const float* __restrict__ Wc2, const float* __restrict__ bc2,
    const float* __restrict__ Wc3, const float* __restrict__ bc3,
    const float* __restrict__ Wc4, const float* __restrict__ bc4)
{
    int id = blockIdx.x * blockDim.x + threadIdx.x;
    if (id == 0) g_ticket = 0u;

    auto getw = [&](int ch, int k) -> float {
        if (ch < 2)  return Wa [ ch        * H + k];
        if (ch < 6)  return Wb [(ch - 2)  * H + k];
        if (ch < 8)  return Wc1[(ch - 6)  * H + k];
        if (ch < 11) return Wc2[(ch - 8)  * H + k];
        if (ch < 15) return Wc3[(ch - 11) * H + k];
        return Wc4[(ch - 15) * H + k];
    };

    if (id < H * 4) {
        int k = id >> 2, p = id & 3;
        g_pack4[id] = make_float4(getw(4 * p, k),     getw(4 * p + 1, k),
                                  getw(4 * p + 2, k), getw(4 * p + 3, k));
    }
    if (id < H) g_pack1[id] = getw(16, id);
    if (id < 17) {
        int ch = id; float b;
        if      (ch < 2)  b = ba [ch];
        else if (ch < 6)  b = bb [ch - 2];
        else if (ch < 8)  b = bc1[ch - 6];
        else if (ch < 11) b = bc2[ch - 8];
        else if (ch < 15) b = bc3[ch - 11];
        else              b = bc4[ch - 15];
        g_biasStage[ch] = b;
    }
}

// ---------------------------------------------------------------------------
__device__ __forceinline__ void ffma2(float2& d, const float2 a, const float2 b)
{
    asm("fma.rn.f32x2 %0, %1, %2, %0;"
        : "+l"(reinterpret_cast<unsigned long long&>(d))
        : "l"(reinterpret_cast<const unsigned long long&>(a)),
          "l"(reinterpret_cast<const unsigned long long&>(b)));
}

__device__ __forceinline__ void cp16(uint32_t saddr, const void* gptr)
{
    asm volatile("cp.async.cg.shared.global [%0], [%1], 16;"
                 :: "r"(saddr), "l"(gptr) : "memory");
}
__device__ __forceinline__ void cp_commit()
{
    asm volatile("cp.async.commit_group;" ::: "memory");
}
template <int N>
__device__ __forceinline__ void cp_wait()
{
    asm volatile("cp.async.wait_group %0;" :: "n"(N) : "memory");
}

// ---------------------------------------------------------------------------
// 128-row pass per warp (4 rows/lane), warp-private 2-deep cp.async ring,
// weights from constant amortized 4x (one 5-LDC fetch feeds 36 fma-insts).
// Warp-level ticket balances 1024 passes over 1184 resident warps.
// ---------------------------------------------------------------------------
extern __shared__ float xs[];

__global__ void __launch_bounds__(WARPS * 32, 2)
main_kernel(const float* __restrict__ x, float* __restrict__ out, int B, int npasses)
{
    const int wid  = threadIdx.x >> 5;
    const int lane = threadIdx.x & 31;

    const uint32_t sb =
        (uint32_t)__cvta_generic_to_shared(xs) + wid * (DEPTH * CHUNK_BYTES);
    float* xw = xs + wid * (DEPTH * CHUNK_FLOATS);

    // cp.async mapping: 4 lanes x 16 B cover one 64 B row segment; 8 rows/inst
    const int crow  = lane >> 2;   // 0..7
    const int cpart = lane & 3;    // 0..3

    for (;;) {
        unsigned t;
        if (lane == 0) t = atomicAdd(&g_ticket, 1u);
        t = __shfl_sync(0xffffffffu, t, 0);
        if (t >= (unsigned)npasses) break;

        const int    row0 = (int)t * WROWS;
        const float* gx   = x + (size_t)row0 * H;

        auto load_chunk = [&](int c, int d) {
            const float*   gsrc = gx + c * CK + (size_t)crow * H + cpart * 4;
            const uint32_t dst0 = sb + d * CHUNK_BYTES + crow * ROWB + cpart * 16;
            #pragma unroll
            for (int i = 0; i < 16; ++i) {         // 16 x 8 rows = 128 rows
                if (row0 + i * 8 + crow < B)
                    cp16(dst0 + i * 8 * ROWB, gsrc + (size_t)(i * 8) * H);
            }
        };

        float2 acc[4][8];
        float  a16[4];
        #pragma unroll
        for (int g = 0; g < 4; ++g) {
            #pragma unroll
            for (int p = 0; p < 8; ++p) acc[g][p] = make_float2(0.f, 0.f);
            a16[g] = 0.f;
        }

        cp_wait<0>();                 // drain any leftover groups from prior pass
        load_chunk(0, 0); cp_commit();
        load_chunk(1, 1); cp_commit();

        #pragma unroll 2
        for (int c = 0; c < NCH; ++c) {
            cp_wait<DEPTH - 1>();     // chunk c resident
            __syncwarp();

            const float* xb = xw + (c & 1) * CHUNK_FLOATS;
            const int kc = c * CK;
            #pragma unroll
            for (int rg = 0; rg < 4; ++rg) {
                float4 xv[4];
                #pragma unroll
                for (int g = 0; g < 4; ++g)
                    xv[g] = *reinterpret_cast<const float4*>(
                        xb + (lane + 32 * g) * RSTRIDE + rg * 4);

                const int kb = kc + rg * 4;
                #pragma unroll
                for (int j = 0; j < 4; ++j) {
                    const int k = kb + j;
                    const float4 w0 = c_W4[k][0];
                    const float4 w1 = c_W4[k][1];
                    const float4 w2 = c_W4[k][2];
                    const float4 w3 = c_W4[k][3];
                    const float  wl = c_W1[k];
                    #pragma unroll
                    for (int g = 0; g < 4; ++g) {
                        const float xk = (j == 0) ? xv[g].x : (j == 1) ? xv[g].y
                                       : (j == 2) ? xv[g].z : xv[g].w;
                        const float2 xd = make_float2(xk, xk);
                        ffma2(acc[g][0], xd, make_float2(w0.x, w0.y));
                        ffma2(acc[g][1], xd, make_float2(w0.z, w0.w));
                        ffma2(acc[g][2], xd, make_float2(w1.x, w1.y));
                        ffma2(acc[g][3], xd, make_float2(w1.z, w1.w));
                        ffma2(acc[g][4], xd, make_float2(w2.x, w2.y));
                        ffma2(acc[g][5], xd, make_float2(w2.z, w2.w));
                        ffma2(acc[g][6], xd, make_float2(w3.x, w3.y));
                        ffma2(acc[g][7], xd, make_float2(w3.z, w3.w));
                        a16[g] = fmaf(xk, wl, a16[g]);
                    }
                }
            }
            __syncwarp();

            if (c + DEPTH < NCH) load_chunk(c + DEPTH, c & 1);
            cp_commit();              // empty groups keep wait_group counts exact
        }

        // --- epilogue: bias, routing, masked scattered stores (4 rows/lane) ---
        #pragma unroll
        for (int g = 0; g < 4; ++g) {
            const int r = row0 + lane + 32 * g;
            if (r >= B) continue;

            float v[17];
            #pragma unroll
            for (int p = 0; p < 8; ++p) {
                v[2 * p]     = acc[g][p].x + c_bias[2 * p];
                v[2 * p + 1] = acc[g][p].y + c_bias[2 * p + 1];
            }
            v[16] = a16[g] + c_bias[16];

            const bool active = v[1] > v[0];               // argmax(out_a) != 0

            ((float2*)out)[r] = make_float2(v[0], v[1]);   // out_a

            int pb = 0; float best = v[2];
            if (v[3] > best) { pb = 1; best = v[3]; }
            if (v[4] > best) { pb = 2; best = v[4]; }
            if (v[5] > best) { pb = 3; best = v[5]; }

            float* ob = out + 2 * (size_t)B + 5 * (size_t)r;   // out_b
            ob[0] = 0.0f;
            #pragma unroll
            for (int j = 0; j < 4; ++j) ob[j + 1] = active ? v[2 + j] : 0.0f;

            float* oc = out + 7 * (size_t)B + 11 * (size_t)r;  // out_c
            #pragma unroll
            for (int j = 0; j < 11; ++j) {
                const int hd = (j < 2) ? 0 : (j < 5) ? 1 : (j < 9) ? 2 : 3;
                oc[j] = (active && hd == pb) ? v[6 + j] : 0.0f;
            }
        }
    }
}

// ---------------------------------------------------------------------------
extern "C" void kernel_launch(void* const* d_in, const int* in_sizes, int n_in,
                              void* d_out, int out_size)
{
    const float* x = (const float*)d_in[0];
    const int B = in_sizes[0] / H;

    prep_kernel<<<12, 256>>>(
        (const float*)d_in[1],  (const float*)d_in[2],
        (const float*)d_in[3],  (const float*)d_in[4],
        (const float*)d_in[5],  (const float*)d_in[6],
        (const float*)d_in[7],  (const float*)d_in[8],
        (const float*)d_in[9],  (const float*)d_in[10],
        (const float*)d_in[11], (const float*)d_in[12]);

    void* p4 = nullptr; cudaGetSymbolAddress(&p4, g_pack4);
    void* p1 = nullptr; cudaGetSymbolAddress(&p1, g_pack1);
    void* pb = nullptr; cudaGetSymbolAddress(&pb, g_biasStage);
    cudaMemcpyToSymbolAsync(c_W4,   p4, sizeof(float4) * H * 4, 0,
                            cudaMemcpyDeviceToDevice, 0);
    cudaMemcpyToSymbolAsync(c_W1,   p1, sizeof(float) * H, 0,
                            cudaMemcpyDeviceToDevice, 0);
    cudaMemcpyToSymbolAsync(c_bias, pb, sizeof(float) * 17, 0,
                            cudaMemcpyDeviceToDevice, 0);

    const int npasses = (B + WROWS - 1) / WROWS;   // 1024 for B=131072
    const int grid    = 148 * 2;                   // 2 CTAs/SM, 1184 warp slots

    cudaFuncSetAttribute(main_kernel,
                         cudaFuncAttributeMaxDynamicSharedMemorySize, SMEM_BYTES);
    main_kernel<<<grid, WARPS * 32, SMEM_BYTES>>>(x, (float*)d_out, B, npasses);
}

// round 6
// speedup vs baseline: 3.4247x; 1.6043x over previous
#include <cuda_runtime.h>
#include <cstdint>

#define H        768
#define CK       16                    // K floats per pipeline stage (64 B/row)
#define NCH      (H / CK)              // 48 chunks
#define DEPTH    2                     // cp.async ring stages
#define WROWS    128                   // rows per warp pass (4 per lane)
#define RSTRIDE  20                    // floats per row slot (16 + 4 pad; conflict-free)
#define ROWB     (RSTRIDE * 4)         // 80 B
#define CHUNK_FLOATS (WROWS * RSTRIDE) // 2560
#define CHUNK_BYTES  (CHUNK_FLOATS * 4)
#define WARPS    8                     // warps per CTA (256 threads), 1 CTA/SM
#define W_SLOTS  (H * 5)               // weight float4 slots in smem (60 KB)
#define W_FLOATS (W_SLOTS * 4)
#define SMEM_BYTES (W_SLOTS * 16 + WARPS * DEPTH * CHUNK_BYTES)  // 225280 B

// 17 fused channels: a0,a1 | b0..b3 | c1_0,c1_1 | c2_0..2 | c3_0..3 | c4_0,c4_1
__constant__ float c_bias[17];

__device__ float4 g_pack4[H * 4];      // channels 0..15, [k][p]
__device__ float  g_pack1[H];          // channel 16
__device__ float  g_biasStage[17];
__device__ unsigned int g_ticket;

// ---------------------------------------------------------------------------
__global__ void prep_kernel(
    const float* __restrict__ Wa,  const float* __restrict__ ba,
    const float* __restrict__ Wb,  const float* __restrict__ bb,
    const float* __restrict__ Wc1, const float* __restrict__ bc1,
    const float* __restrict__ Wc2, const float* __restrict__ bc2,
    const float* __restrict__ Wc3, const float* __restrict__ bc3,
    const float* __restrict__ Wc4, const float* __restrict__ bc4)
{
    int id = blockIdx.x * blockDim.x + threadIdx.x;
    if (id == 0) g_ticket = 0u;

    auto getw = [&](int ch, int k) -> float {
        if (ch < 2)  return Wa [ ch        * H + k];
        if (ch < 6)  return Wb [(ch - 2)  * H + k];
        if (ch < 8)  return Wc1[(ch - 6)  * H + k];
        if (ch < 11) return Wc2[(ch - 8)  * H + k];
        if (ch < 15) return Wc3[(ch - 11) * H + k];
        return Wc4[(ch - 15) * H + k];
    };

    if (id < H * 4) {
        int k = id >> 2, p = id & 3;
        g_pack4[id] = make_float4(getw(4 * p, k),     getw(4 * p + 1, k),
                                  getw(4 * p + 2, k), getw(4 * p + 3, k));
    }
    if (id < H) g_pack1[id] = getw(16, id);
    if (id < 17) {
        int ch = id; float b;
        if      (ch < 2)  b = ba [ch];
        else if (ch < 6)  b = bb [ch - 2];
        else if (ch < 8)  b = bc1[ch - 6];
        else if (ch < 11) b = bc2[ch - 8];
        else if (ch < 15) b = bc3[ch - 11];
        else              b = bc4[ch - 15];
        g_biasStage[ch] = b;
    }
}

// ---------------------------------------------------------------------------
__device__ __forceinline__ void ffma2(float2& d, const float2 a, const float2 b)
{
    asm("fma.rn.f32x2 %0, %1, %2, %0;"
        : "+l"(reinterpret_cast<unsigned long long&>(d))
        : "l"(reinterpret_cast<const unsigned long long&>(a)),
          "l"(reinterpret_cast<const unsigned long long&>(b)));
}

__device__ __forceinline__ void cp16(uint32_t saddr, const void* gptr)
{
    asm volatile("cp.async.cg.shared.global [%0], [%1], 16;"
                 :: "r"(saddr), "l"(gptr) : "memory");
}
__device__ __forceinline__ void cp_commit()
{
    asm volatile("cp.async.commit_group;" ::: "memory");
}
template <int N>
__device__ __forceinline__ void cp_wait()
{
    asm volatile("cp.async.wait_group %0;" :: "n"(N) : "memory");
}

// ---------------------------------------------------------------------------
// 128-row pass per warp (4 rows/lane); warp-private 2-deep cp.async ring for x;
// weights resident in shared memory (broadcast LDS, no const-cache thrash).
// One 256-thread CTA per SM; warp-level ticket over 1024 passes.
// ---------------------------------------------------------------------------
extern __shared__ float smem[];

__global__ void __launch_bounds__(WARPS * 32, 1)
main_kernel(const float* __restrict__ x, float* __restrict__ out, int B, int npasses)
{
    const int wid  = threadIdx.x >> 5;
    const int lane = threadIdx.x & 31;

    float4* sw    = reinterpret_cast<float4*>(smem);        // [H][5] float4
    float*  xbase = smem + W_FLOATS;

    // ---- stage weights into smem once per CTA ----
    for (int i = threadIdx.x; i < W_SLOTS; i += WARPS * 32) {
        const int k = i / 5, p = i - k * 5;
        sw[i] = (p < 4) ? g_pack4[k * 4 + p]
                        : make_float4(g_pack1[k], 0.f, 0.f, 0.f);
    }
    __syncthreads();

    const uint32_t sb = (uint32_t)__cvta_generic_to_shared(xbase)
                        + wid * (DEPTH * CHUNK_BYTES);
    float* xw = xbase + wid * (DEPTH * CHUNK_FLOATS);

    // cp.async mapping: 4 lanes x 16 B cover one 64 B row segment; 8 rows/inst
    const int crow  = lane >> 2;   // 0..7
    const int cpart = lane & 3;    // 0..3

    for (;;) {
        unsigned t;
        if (lane == 0) t = atomicAdd(&g_ticket, 1u);
        t = __shfl_sync(0xffffffffu, t, 0);
        if (t >= (unsigned)npasses) break;

        const int    row0 = (int)t * WROWS;
        const float* gx   = x + (size_t)row0 * H;

        auto load_chunk = [&](int c, int d) {
            const float*   gsrc = gx + c * CK + (size_t)crow * H + cpart * 4;
            const uint32_t dst0 = sb + d * CHUNK_BYTES + crow * ROWB + cpart * 16;
            #pragma unroll
            for (int i = 0; i < 16; ++i) {         // 16 x 8 rows = 128 rows
                if (row0 + i * 8 + crow < B)
                    cp16(dst0 + i * 8 * ROWB, gsrc + (size_t)(i * 8) * H);
            }
        };

        float2 acc[4][8];
        float  a16[4];
        #pragma unroll
        for (int g = 0; g < 4; ++g) {
            #pragma unroll
            for (int p = 0; p < 8; ++p) acc[g][p] = make_float2(0.f, 0.f);
            a16[g] = 0.f;
        }

        cp_wait<0>();                 // drain leftover groups from prior pass
        load_chunk(0, 0); cp_commit();
        load_chunk(1, 1); cp_commit();

        #pragma unroll 2
        for (int c = 0; c < NCH; ++c) {
            cp_wait<DEPTH - 1>();     // chunk c resident
            __syncwarp();

            const float* xb = xw + (c & 1) * CHUNK_FLOATS;
            const int kc = c * CK;
            #pragma unroll
            for (int rg = 0; rg < 4; ++rg) {
                float4 xv[4];
                #pragma unroll
                for (int g = 0; g < 4; ++g)
                    xv[g] = *reinterpret_cast<const float4*>(
                        xb + (lane + 32 * g) * RSTRIDE + rg * 4);

                const int kb = kc + rg * 4;
                #pragma unroll
                for (int j = 0; j < 4; ++j) {
                    const float4* wk = sw + (kb + j) * 5;   // warp-uniform -> broadcast LDS
                    const float4 w0 = wk[0];
                    const float4 w1 = wk[1];
                    const float4 w2 = wk[2];
                    const float4 w3 = wk[3];
                    const float  wl = wk[4].x;
                    #pragma unroll
                    for (int g = 0; g < 4; ++g) {
                        const float xk = (j == 0) ? xv[g].x : (j == 1) ? xv[g].y
                                       : (j == 2) ? xv[g].z : xv[g].w;
                        const float2 xd = make_float2(xk, xk);
                        ffma2(acc[g][0], xd, make_float2(w0.x, w0.y));
                        ffma2(acc[g][1], xd, make_float2(w0.z, w0.w));
                        ffma2(acc[g][2], xd, make_float2(w1.x, w1.y));
                        ffma2(acc[g][3], xd, make_float2(w1.z, w1.w));
                        ffma2(acc[g][4], xd, make_float2(w2.x, w2.y));
                        ffma2(acc[g][5], xd, make_float2(w2.z, w2.w));
                        ffma2(acc[g][6], xd, make_float2(w3.x, w3.y));
                        ffma2(acc[g][7], xd, make_float2(w3.z, w3.w));
                        a16[g] = fmaf(xk, wl, a16[g]);
                    }
                }
            }
            __syncwarp();

            if (c + DEPTH < NCH) load_chunk(c + DEPTH, c & 1);
            cp_commit();              // empty groups keep wait_group counts exact
        }

        // --- epilogue: bias, routing, masked scattered stores (4 rows/lane) ---
        #pragma unroll
        for (int g = 0; g < 4; ++g) {
            const int r = row0 + lane + 32 * g;
            if (r >= B) continue;

            float v[17];
            #pragma unroll
            for (int p = 0; p < 8; ++p) {
                v[2 * p]     = acc[g][p].x + c_bias[2 * p];
                v[2 * p + 1] = acc[g][p].y + c_bias[2 * p + 1];
            }
            v[16] = a16[g] + c_bias[16];

            const bool active = v[1] > v[0];               // argmax(out_a) != 0

            ((float2*)out)[r] = make_float2(v[0], v[1]);   // out_a

            int pb = 0; float best = v[2];
            if (v[3] > best) { pb = 1; best = v[3]; }
            if (v[4] > best) { pb = 2; best = v[4]; }
            if (v[5] > best) { pb = 3; best = v[5]; }

            float* ob = out + 2 * (size_t)B + 5 * (size_t)r;   // out_b
            ob[0] = 0.0f;
            #pragma unroll
            for (int j = 0; j < 4; ++j) ob[j + 1] = active ? v[2 + j] : 0.0f;

            float* oc = out + 7 * (size_t)B + 11 * (size_t)r;  // out_c
            #pragma unroll
            for (int j = 0; j < 11; ++j) {
                const int hd = (j < 2) ? 0 : (j < 5) ? 1 : (j < 9) ? 2 : 3;
                oc[j] = (active && hd == pb) ? v[6 + j] : 0.0f;
            }
        }
    }
}

// ---------------------------------------------------------------------------
extern "C" void kernel_launch(void* const* d_in, const int* in_sizes, int n_in,
                              void* d_out, int out_size)
{
    const float* x = (const float*)d_in[0];
    const int B = in_sizes[0] / H;

    prep_kernel<<<12, 256>>>(
        (const float*)d_in[1],  (const float*)d_in[2],
        (const float*)d_in[3],  (const float*)d_in[4],
        (const float*)d_in[5],  (const float*)d_in[6],
        (const float*)d_in[7],  (const float*)d_in[8],
        (const float*)d_in[9],  (const float*)d_in[10],
        (const float*)d_in[11], (const float*)d_in[12]);

    void* pb = nullptr; cudaGetSymbolAddress(&pb, g_biasStage);
    cudaMemcpyToSymbolAsync(c_bias, pb, sizeof(float) * 17, 0,
                            cudaMemcpyDeviceToDevice, 0);

    const int npasses = (B + WROWS - 1) / WROWS;   // 1024 for B=131072
    const int grid    = 148;                        // 1 CTA/SM, 1184 warp slots

    cudaFuncSetAttribute(main_kernel,
                         cudaFuncAttributeMaxDynamicSharedMemorySize, SMEM_BYTES);
    main_kernel<<<grid, WARPS * 32, SMEM_BYTES>>>(x, (float*)d_out, B, npasses);
}